// round 3
// baseline (speedup 1.0000x reference)
#include <cuda_runtime.h>

// Problem constants
#define T_STEPS 512
#define B_TOTAL 512
#define I_DIM   32
#define H_DIM   64
#define G_DIM   256   // 4*H
#define HX_DIM  96    // concatenated [h(64); x(32)]
#define NT      8     // num tickers

typedef unsigned long long u64;

// Packed fp32x2 FMA (Blackwell): 2 FMAs per instruction on the fma pipe.
__device__ __forceinline__ u64 ffma2(u64 a, u64 b, u64 c) {
    u64 d;
    asm("fma.rn.f32x2 %0, %1, %2, %3;" : "=l"(d) : "l"(a), "l"(b), "l"(c));
    return d;
}
__device__ __forceinline__ u64 pack2(float lo, float hi) {
    u64 d;
    asm("mov.b64 %0, {%1, %2};" : "=l"(d) : "f"(lo), "f"(hi));
    return d;
}
__device__ __forceinline__ void unpack2(u64 v, float& lo, float& hi) {
    asm("mov.b64 {%0, %1}, %2;" : "=f"(lo), "=f"(hi) : "l"(v));
}
__device__ __forceinline__ void barx(int id) {
    asm volatile("bar.sync %0, 256;" :: "r"(id) : "memory");
}
__device__ __forceinline__ float fast_sigmoid(float x) {
    return 1.0f / (1.0f + __expf(-x));
}
__device__ __forceinline__ float fast_tanh(float x) {
    return 1.0f - 2.0f / (__expf(2.0f * x) + 1.0f);  // stable for large |x|
}

// ---------------------------------------------------------------------------
// Fused LSTM, k-split edition.
// 128 CTAs x 512 threads. CTA owns 4 batch rows as two independent 256-thread
// halves (2 batches each, own named barrier). Within a half:
//   lane pair (j, ks=lane&1): gate pair (2j, 2j+1); ks splits the 96-dim
//   [h;x] dot product in half (48 dims each), reduced via shfl_xor(1).
//   Weights [W_hh | W_ih] rows packed as 48 u64 regs per thread.
//   h and x live DUPLICATED {v,v} in one smem array hx[b][96] -> broadcast
//   LDS.128 feeds ffma2 directly.
//   x(t+1..t+3) prefetched into regs by staging warps, dropped to smem in the
//   elementwise phase.
// ---------------------------------------------------------------------------
__global__ __launch_bounds__(512, 1) void fused_lstm_kernel(
    const float* __restrict__ x,    const float* __restrict__ w_ih,
    const float* __restrict__ w_hh, const float* __restrict__ b_ih,
    const float* __restrict__ b_hh, const float* __restrict__ w_fc,
    const float* __restrict__ b_fc, float* __restrict__ out)
{
    __shared__ __align__(16) u64   hx[2][2][HX_DIM];     // [half][b][dim] = {v,v}
    __shared__ __align__(16) float gates[2][2][G_DIM];   // [half][b][g]

    const int tid  = threadIdx.x;
    const int half = tid >> 8;       // 0 or 1
    const int ht   = tid & 255;      // thread within half
    const int ks   = ht & 1;         // k-split (lane parity)
    const int j    = ht >> 1;        // gate-pair index [0,128)
    const int B0   = blockIdx.x * 4;
    const int bb   = B0 + half * 2;  // first batch of this half

    // ---- pack [W_hh | W_ih] rows 2j, 2j+1, dims [48*ks, 48*ks+48) ----
    u64 w[48];
    {
        const float* rh0 = w_hh + (2 * j)     * H_DIM;
        const float* rh1 = w_hh + (2 * j + 1) * H_DIM;
        const float* ri0 = w_ih + (2 * j)     * I_DIM;
        const float* ri1 = w_ih + (2 * j + 1) * I_DIM;
        const int d0 = ks * 48;
        #pragma unroll
        for (int k = 0; k < 48; k++) {
            int d = d0 + k;
            float a, b;
            if (d < H_DIM) { a = rh0[d]; b = rh1[d]; }
            else           { a = ri0[d - H_DIM]; b = ri1[d - H_DIM]; }
            w[k] = pack2(a, b);
        }
    }
    // bias contributed only by the ks=0 lane of each pair
    const u64 bias2 = ks ? 0ULL
                         : pack2(b_ih[2 * j] + b_hh[2 * j],
                                 b_ih[2 * j + 1] + b_hh[2 * j + 1]);

    // ---- roles ----
    const int be = (ht >> 6) & 1;     // elementwise batch (ht < 128 only)
    const int ke = ht & 63;           // elementwise hidden index
    const bool is_elem  = (ht < 128);
    const int  st       = ht - 128;
    const bool is_stage = (ht >= 128) && (st < 64);
    const int bq = (st >> 5) & 1, iq = st & 31;

    // ---- init h = 0, stage x(0), preload x(1..3) into regs ----
    if (is_elem) hx[half][be][ke] = 0ULL;
    float xr0 = 0.f, xr1 = 0.f, xr2 = 0.f;
    const float* xbase = x + ((size_t)(bb + bq) * T_STEPS) * I_DIM + iq;
    if (is_stage) {
        float v0 = xbase[0];
        hx[half][bq][H_DIM + iq] = pack2(v0, v0);
        xr0 = xbase[1 * I_DIM];
        xr1 = xbase[2 * I_DIM];
        xr2 = xbase[3 * I_DIM];
    }
    float c_val = 0.0f;
    barx(1 + half);

    const u64*  h0p = hx[half][0] + ks * 48;
    const u64*  h1p = hx[half][1] + ks * 48;
    float*      gst = &gates[half][ks][2 * j];
    const float* gb = &gates[half][be][0];

    for (int t = 0; t < T_STEPS; t++) {
        // ---- half-dot over 48 dims of [h;x], both batches ----
        u64 acc0 = bias2, acc1 = bias2;
        #pragma unroll
        for (int k = 0; k < 48; k += 2) {
            ulonglong2 v0 = *(const ulonglong2*)(h0p + k);
            ulonglong2 v1 = *(const ulonglong2*)(h1p + k);
            acc0 = ffma2(w[k], v0.x, acc0); acc0 = ffma2(w[k + 1], v0.y, acc0);
            acc1 = ffma2(w[k], v1.x, acc1); acc1 = ffma2(w[k + 1], v1.y, acc1);
        }
        // ---- butterfly reduce across the ks pair (same warp, lane^1) ----
        float a0lo, a0hi, a1lo, a1hi;
        unpack2(acc0, a0lo, a0hi);
        unpack2(acc1, a1lo, a1hi);
        a0lo += __shfl_xor_sync(0xffffffffu, a0lo, 1);
        a0hi += __shfl_xor_sync(0xffffffffu, a0hi, 1);
        a1lo += __shfl_xor_sync(0xffffffffu, a1lo, 1);
        a1hi += __shfl_xor_sync(0xffffffffu, a1hi, 1);
        // lane ks stores batch ks's gate pair (both lanes hold full sums)
        *(u64*)gst = ks ? pack2(a1lo, a1hi) : pack2(a0lo, a0hi);

        barx(1 + half);   // gates visible; all hx reads of this step done

        if (is_elem) {
            // PyTorch gate order i,f,g,o
            float i_a = fast_sigmoid(gb[ke]);
            float f_a = fast_sigmoid(gb[64 + ke]);
            float g_a = fast_tanh   (gb[128 + ke]);
            float o_a = fast_sigmoid(gb[192 + ke]);
            c_val = f_a * c_val + i_a * g_a;
            float h = o_a * fast_tanh(c_val);
            hx[half][be][ke] = pack2(h, h);
        } else if (is_stage) {
            // drop x(t+1) into smem; refill prefetch ring with x(t+4)
            hx[half][bq][H_DIM + iq] = pack2(xr0, xr0);
            xr0 = xr1; xr1 = xr2;
            if (t + 4 < T_STEPS) xr2 = xbase[(size_t)(t + 4) * I_DIM];
        }

        barx(1 + half);   // h(t+1), x(t+1) visible
    }

    __syncthreads();   // join halves for the FC

    // ---- final FC: out[b][n] = h_last[b] . w_fc[n] + b_fc[n] ----
    if (tid < 4 * NT) {
        int b = tid >> 3, n = tid & 7;
        int fh = b >> 1, fb = b & 1;
        float s = b_fc[n];
        const float* wf = w_fc + n * H_DIM;
        #pragma unroll
        for (int k = 0; k < H_DIM; k++) {
            float lo, hi;
            unpack2(hx[fh][fb][k], lo, hi);
            s += lo * wf[k];
        }
        out[(B0 + b) * NT + n] = s;
    }
}

// ---------------------------------------------------------------------------
extern "C" void kernel_launch(void* const* d_in, const int* in_sizes, int n_in,
                              void* d_out, int out_size)
{
    const float* x    = (const float*)d_in[0];
    const float* w_ih = (const float*)d_in[1];
    const float* w_hh = (const float*)d_in[2];
    const float* b_ih = (const float*)d_in[3];
    const float* b_hh = (const float*)d_in[4];
    const float* w_fc = (const float*)d_in[5];
    const float* b_fc = (const float*)d_in[6];
    float* out = (float*)d_out;

    (void)in_sizes; (void)n_in; (void)out_size;

    fused_lstm_kernel<<<B_TOTAL / 4, 512>>>(x, w_ih, w_hh, b_ih, b_hh,
                                            w_fc, b_fc, out);
}

// round 4
// speedup vs baseline: 1.2390x; 1.2390x over previous
#include <cuda_runtime.h>

// Problem constants
#define T_STEPS 512
#define B_TOTAL 512
#define I_DIM   32
#define H_DIM   64
#define G_DIM   256   // 4*H
#define HX_DIM  96    // concatenated [h(64); x(32)]
#define NT      8     // num tickers

typedef unsigned long long u64;

// Packed fp32x2 FMA (Blackwell): 2 FMAs per instruction on the fma pipe.
__device__ __forceinline__ u64 ffma2(u64 a, u64 b, u64 c) {
    u64 d;
    asm("fma.rn.f32x2 %0, %1, %2, %3;" : "=l"(d) : "l"(a), "l"(b), "l"(c));
    return d;
}
__device__ __forceinline__ u64 pack2(float lo, float hi) {
    u64 d;
    asm("mov.b64 %0, {%1, %2};" : "=l"(d) : "f"(lo), "f"(hi));
    return d;
}
__device__ __forceinline__ void unpack2(u64 v, float& lo, float& hi) {
    asm("mov.b64 {%0, %1}, %2;" : "=f"(lo), "=f"(hi) : "l"(v));
}
__device__ __forceinline__ float fast_sigmoid(float x) {
    return 1.0f / (1.0f + __expf(-x));
}
__device__ __forceinline__ float fast_tanh(float x) {
    return 1.0f - 2.0f / (__expf(2.0f * x) + 1.0f);  // stable for large |x|
}

// ---------------------------------------------------------------------------
// Two-group software-pipelined LSTM. 128 CTAs x 256 threads.
// CTA owns 4 batch rows = 2 groups x 2 batches. 2*T phases; phase p (G=p&1):
//   - ALL threads: matvec for group G, step p>>1:
//       thread (j = tid&127, bsel = tid>>7) computes gate pair (2j,2j+1) of
//       batch bsel via a 96-dim [h;x] dot, weights packed in 96 u64 regs,
//       operands read from smem as broadcast {v,v} pairs (LDS.128).
//   - threads with eg==G^1: elementwise LSTM cell for group G^1 (gates were
//     produced last phase) -> writes h into hx[G^1]. Independent of the
//     matvec above, so it fills the matvec chain's stall slots.
//   - threads with eg==G (free half): stage x(G^1, next step) into hx[G^1]'s
//     x-region (never read this phase).
//   - one __syncthreads per phase.
// ---------------------------------------------------------------------------
__global__ __launch_bounds__(256, 1) void fused_lstm_kernel(
    const float* __restrict__ x,    const float* __restrict__ w_ih,
    const float* __restrict__ w_hh, const float* __restrict__ b_ih,
    const float* __restrict__ b_hh, const float* __restrict__ w_fc,
    const float* __restrict__ b_fc, float* __restrict__ out)
{
    __shared__ __align__(16) u64   hx[2][2][HX_DIM];     // [grp][b][dim] = {v,v}
    __shared__ __align__(16) float gates[2][2][G_DIM];   // [grp][b][g]

    const int tid  = threadIdx.x;
    const int j    = tid & 127;    // gate-pair index
    const int bsel = tid >> 7;     // batch within the matvec group
    const int eg   = tid >> 7;     // elem/staging group identity
    const int B0   = blockIdx.x * 4;

    // ---- pack [W_hh | W_ih] rows 2j, 2j+1 into 96 u64 regs ----
    u64 w[HX_DIM];
    {
        const float* rh0 = w_hh + (2 * j)     * H_DIM;
        const float* rh1 = w_hh + (2 * j + 1) * H_DIM;
        #pragma unroll
        for (int k = 0; k < H_DIM; k++) w[k] = pack2(rh0[k], rh1[k]);
        const float* ri0 = w_ih + (2 * j)     * I_DIM;
        const float* ri1 = w_ih + (2 * j + 1) * I_DIM;
        #pragma unroll
        for (int i = 0; i < I_DIM; i++) w[H_DIM + i] = pack2(ri0[i], ri1[i]);
    }
    const u64 bias2 = pack2(b_ih[2 * j] + b_hh[2 * j],
                            b_ih[2 * j + 1] + b_hh[2 * j + 1]);

    // ---- elementwise identity: thread handles (eg, be, ke) ----
    const int be = (tid >> 6) & 1;
    const int ke = tid & 63;
    float c_val = 0.0f;
    const float* gb = &gates[eg][be][0];

    // ---- staging identity: free-half threads stage x for group eg^1 ----
    const int  ht = tid & 127;
    const bool is_stage = (ht < 64);
    const int  bq = ht >> 5, iq = ht & 31;
    const int  sg = eg ^ 1;
    const float* sx = x + ((size_t)(B0 + 2 * sg + bq) * T_STEPS) * I_DIM + iq;
    float xr = 0.0f;
    if (is_stage) xr = sx[(size_t)eg * I_DIM];   // eg=0 -> x(B,0), eg=1 -> x(A,1)

    // ---- init smem: h = 0 (both groups), x(A,0) preloaded ----
    hx[tid >> 7][(tid >> 6) & 1][tid & 63] = 0ULL;   // covers 2*2*64 h-slots
    if (tid < 64) {
        float v = x[((size_t)(B0 + (tid >> 5)) * T_STEPS) * I_DIM + (tid & 31)];
        hx[0][tid >> 5][H_DIM + (tid & 31)] = pack2(v, v);
    }
    __syncthreads();

    for (int p = 0; p < 2 * T_STEPS; p++) {
        const int G = p & 1;

        // ---- matvec(G, p>>1): 96-dim [h;x] dot, all threads ----
        u64 acc = bias2;
        const u64* v = hx[G][bsel];
        #pragma unroll
        for (int k = 0; k < HX_DIM; k += 2) {
            ulonglong2 vv = *(const ulonglong2*)(v + k);
            acc = ffma2(w[k],     vv.x, acc);
            acc = ffma2(w[k + 1], vv.y, acc);
        }
        *(u64*)&gates[G][bsel][2 * j] = acc;

        if (eg == (G ^ 1)) {
            // ---- elementwise cell for group eg, using last phase's gates ----
            if (p > 0) {
                float i_a = fast_sigmoid(gb[ke]);
                float f_a = fast_sigmoid(gb[64 + ke]);
                float g_a = fast_tanh   (gb[128 + ke]);
                float o_a = fast_sigmoid(gb[192 + ke]);
                c_val = f_a * c_val + i_a * g_a;
                float h = o_a * fast_tanh(c_val);
                hx[eg][be][ke] = pack2(h, h);
            }
        } else if (is_stage) {
            // ---- stage x(G^1, (p+1)>>1); refill prefetch ----
            const int ts = (p + 1) >> 1;
            hx[sg][bq][H_DIM + iq] = pack2(xr, xr);
            if (ts + 1 < T_STEPS) xr = sx[(size_t)(ts + 1) * I_DIM];
        }

        __syncthreads();
    }

    // ---- drain: elementwise for group 1, step T-1 ----
    if (eg == 1) {
        float i_a = fast_sigmoid(gb[ke]);
        float f_a = fast_sigmoid(gb[64 + ke]);
        float g_a = fast_tanh   (gb[128 + ke]);
        float o_a = fast_sigmoid(gb[192 + ke]);
        c_val = f_a * c_val + i_a * g_a;
        float h = o_a * fast_tanh(c_val);
        hx[1][be][ke] = pack2(h, h);
    }
    __syncthreads();

    // ---- final FC: out[b][n] = h_last[b] . w_fc[n] + b_fc[n] ----
    if (tid < 4 * NT) {
        int b = tid >> 3, n = tid & 7;
        int fg = b >> 1, fb = b & 1;
        float s = b_fc[n];
        const float* wf = w_fc + n * H_DIM;
        #pragma unroll
        for (int k = 0; k < H_DIM; k++) {
            float lo, hi;
            unpack2(hx[fg][fb][k], lo, hi);
            s += lo * wf[k];
        }
        out[(B0 + b) * NT + n] = s;
    }
}

// ---------------------------------------------------------------------------
extern "C" void kernel_launch(void* const* d_in, const int* in_sizes, int n_in,
                              void* d_out, int out_size)
{
    const float* x    = (const float*)d_in[0];
    const float* w_ih = (const float*)d_in[1];
    const float* w_hh = (const float*)d_in[2];
    const float* b_ih = (const float*)d_in[3];
    const float* b_hh = (const float*)d_in[4];
    const float* w_fc = (const float*)d_in[5];
    const float* b_fc = (const float*)d_in[6];
    float* out = (float*)d_out;

    (void)in_sizes; (void)n_in; (void)out_size;

    fused_lstm_kernel<<<B_TOTAL / 4, 256>>>(x, w_ih, w_hh, b_ih, b_hh,
                                            w_fc, b_fc, out);
}

// round 6
// speedup vs baseline: 1.4825x; 1.1965x over previous
#include <cuda_runtime.h>

// Problem constants
#define T_STEPS 512
#define B_TOTAL 512
#define I_DIM   32
#define H_DIM   64
#define G_DIM   256   // 4*H
#define HX_DIM  96    // concatenated [h(64); x(32)]
#define NT      8     // num tickers

typedef unsigned long long u64;

__device__ __forceinline__ u64 ffma2(u64 a, u64 b, u64 c) {
    u64 d;
    asm("fma.rn.f32x2 %0, %1, %2, %3;" : "=l"(d) : "l"(a), "l"(b), "l"(c));
    return d;
}
__device__ __forceinline__ u64 pack2(float lo, float hi) {
    u64 d;
    asm("mov.b64 %0, {%1, %2};" : "=l"(d) : "f"(lo), "f"(hi));
    return d;
}
__device__ __forceinline__ void unpack2(u64 v, float& lo, float& hi) {
    asm("mov.b64 {%0, %1}, %2;" : "=f"(lo), "=f"(hi) : "l"(v));
}
__device__ __forceinline__ void barx(int id) {
    asm volatile("bar.sync %0, 128;" :: "r"(id) : "memory");
}
__device__ __forceinline__ float fast_sigmoid(float x) {
    return 1.0f / (1.0f + __expf(-x));
}
__device__ __forceinline__ float fast_tanh(float x) {
    return 1.0f - 2.0f / (__expf(2.0f * x) + 1.0f);  // stable for large |x|
}

// ---------------------------------------------------------------------------
// Fused LSTM. 128 CTAs x 256 threads; CTA = two INDEPENDENT 128-thread halves
// (2 batches each, own named barrier). Half 1 runs one redundant dummy matvec
// before the loop (deterministic ~400cyc skew, no clock()) so the halves run
// anti-phase: one half's matvec overlaps the other's elementwise/barrier time.
// Matvec thread (q = ht>>6, kj = ht&63) computes gates (2q*64+kj, (2q+1)*64+kj)
// -> q=0 gives {i,f}, q=1 gives {g,o}; elem reads all 4 gates with ONE LDS.128.
// [W_hh|W_ih] rows packed in 96 u64 regs; operands hx[b][96] stored {v,v};
// x prefetched via a register ring (depth 4) so no LDG latency is ever exposed
// inside the barrier-bounded phase.
// ---------------------------------------------------------------------------
__global__ __launch_bounds__(256, 1) void fused_lstm_kernel(
    const float* __restrict__ x,    const float* __restrict__ w_ih,
    const float* __restrict__ w_hh, const float* __restrict__ b_ih,
    const float* __restrict__ b_hh, const float* __restrict__ w_fc,
    const float* __restrict__ b_fc, float* __restrict__ out)
{
    __shared__ __align__(16) u64 hx[2][2][HX_DIM];     // [half][b][dim] = {v,v}
    __shared__ __align__(16) u64 gates4[2][2][128];    // [half][b][kj*2+q] = gate pair
    __shared__ u64 sink;                               // dummy-matvec sink

    const int tid  = threadIdx.x;
    const int half = tid >> 7;
    const int ht   = tid & 127;
    const int q    = ht >> 6;       // gate-quad selector (0: {i,f}, 1: {g,o})
    const int kj   = ht & 63;       // hidden index within quad
    const int g0   = (2 * q) * 64 + kj;
    const int g1   = (2 * q + 1) * 64 + kj;
    const int B0   = blockIdx.x * 4;
    const int bb   = B0 + half * 2;

    // ---- pack [W_hh | W_ih] rows g0, g1 into 96 u64 regs ----
    u64 w[HX_DIM];
    {
        const float* rh0 = w_hh + g0 * H_DIM;
        const float* rh1 = w_hh + g1 * H_DIM;
        #pragma unroll
        for (int k = 0; k < H_DIM; k++) w[k] = pack2(rh0[k], rh1[k]);
        const float* ri0 = w_ih + g0 * I_DIM;
        const float* ri1 = w_ih + g1 * I_DIM;
        #pragma unroll
        for (int i = 0; i < I_DIM; i++) w[H_DIM + i] = pack2(ri0[i], ri1[i]);
    }
    const u64 bias2 = pack2(b_ih[g0] + b_hh[g0], b_ih[g1] + b_hh[g1]);

    // ---- elem identity (all 128 threads of the half) ----
    const int be = ht >> 6;         // batch for elementwise
    const int ke = ht & 63;
    float c_val = 0.0f;

    // ---- staging identity (ht < 64): x for batch bq, input dim iq ----
    const bool is_stage = (ht < 64);
    const int  bq = ht >> 5, iq = ht & 31;
    const float* sx = x + ((size_t)(bb + bq) * T_STEPS) * I_DIM + iq;
    float xr0 = 0.f, xr1 = 0.f, xr2 = 0.f;

    // ---- init: h = 0, x(0) staged, x(1..3) preloaded into regs ----
    hx[half][be][ke] = 0ULL;        // covers all 2*2*64 h slots
    if (is_stage) {
        float v0 = sx[0];
        hx[half][bq][H_DIM + iq] = pack2(v0, v0);
        xr0 = sx[1 * I_DIM];
        xr1 = sx[2 * I_DIM];
        xr2 = sx[3 * I_DIM];
    }
    barx(1 + half);

    const u64* v0p = hx[half][0];
    const u64* v1p = hx[half][1];
    u64* gs0 = &gates4[half][0][kj * 2 + q];
    u64* gs1 = &gates4[half][1][kj * 2 + q];
    const u64* ge = &gates4[half][be][ke * 2];

    // ---- deterministic anti-phase skew: half 1 does one dummy matvec ----
    if (half == 1) {
        u64 acc0 = bias2, acc1 = bias2;
        #pragma unroll
        for (int k = 0; k < HX_DIM; k += 2) {
            ulonglong2 a = *(const ulonglong2*)(v0p + k);
            ulonglong2 b = *(const ulonglong2*)(v1p + k);
            acc0 = ffma2(w[k], a.x, acc0); acc0 = ffma2(w[k + 1], a.y, acc0);
            acc1 = ffma2(w[k], b.x, acc1); acc1 = ffma2(w[k + 1], b.y, acc1);
        }
        if (acc0 + acc1 == 0x7ff123ULL)   // never true for finite inputs
            *(volatile u64*)&sink = acc0;
    }

    for (int t = 0; t < T_STEPS; t++) {
        // ---- matvec: 96-dim [h;x] dots for both batches (2 indep chains) ----
        u64 acc0 = bias2, acc1 = bias2;
        #pragma unroll
        for (int k = 0; k < HX_DIM; k += 2) {
            ulonglong2 a = *(const ulonglong2*)(v0p + k);
            ulonglong2 b = *(const ulonglong2*)(v1p + k);
            acc0 = ffma2(w[k], a.x, acc0); acc0 = ffma2(w[k + 1], a.y, acc0);
            acc1 = ffma2(w[k], b.x, acc1); acc1 = ffma2(w[k + 1], b.y, acc1);
        }
        *gs0 = acc0;
        *gs1 = acc1;

        barx(1 + half);   // gates visible; all hx reads of step t complete

        // ---- elementwise cell: ONE LDS.128 yields {i,f},{g,o} ----
        {
            ulonglong2 g4 = *(const ulonglong2*)ge;
            float gi, gf, gg, go;
            unpack2(g4.x, gi, gf);
            unpack2(g4.y, gg, go);
            float i_a = fast_sigmoid(gi);
            float f_a = fast_sigmoid(gf);
            float g_a = fast_tanh(gg);
            float o_a = fast_sigmoid(go);
            c_val = f_a * c_val + i_a * g_a;
            float h = o_a * fast_tanh(c_val);
            hx[half][be][ke] = pack2(h, h);
        }

        // ---- stage x(t+1) from the register ring; refill with x(t+4) ----
        if (is_stage) {
            if (t + 1 < T_STEPS) hx[half][bq][H_DIM + iq] = pack2(xr0, xr0);
            xr0 = xr1; xr1 = xr2;
            if (t + 4 < T_STEPS) xr2 = sx[(size_t)(t + 4) * I_DIM];
        }

        barx(1 + half);   // h(t+1), x(t+1) visible
    }

    __syncthreads();   // join halves for the FC

    // ---- final FC: out[b][n] = h_last[b] . w_fc[n] + b_fc[n] ----
    if (tid < 4 * NT) {
        int b = tid >> 3, n = tid & 7;
        int fh = b >> 1, fb = b & 1;
        float s = b_fc[n];
        const float* wf = w_fc + n * H_DIM;
        #pragma unroll
        for (int k = 0; k < H_DIM; k++) {
            float lo, hi;
            unpack2(hx[fh][fb][k], lo, hi);
            s += lo * wf[k];
        }
        out[(B0 + b) * NT + n] = s;
    }
}

// ---------------------------------------------------------------------------
extern "C" void kernel_launch(void* const* d_in, const int* in_sizes, int n_in,
                              void* d_out, int out_size)
{
    const float* x    = (const float*)d_in[0];
    const float* w_ih = (const float*)d_in[1];
    const float* w_hh = (const float*)d_in[2];
    const float* b_ih = (const float*)d_in[3];
    const float* b_hh = (const float*)d_in[4];
    const float* w_fc = (const float*)d_in[5];
    const float* b_fc = (const float*)d_in[6];
    float* out = (float*)d_out;

    (void)in_sizes; (void)n_in; (void)out_size;

    fused_lstm_kernel<<<B_TOTAL / 4, 256>>>(x, w_ih, w_hh, b_ih, b_hh,
                                            w_fc, b_fc, out);
}

// round 8
// speedup vs baseline: 1.6502x; 1.1131x over previous
#include <cuda_runtime.h>

// Problem constants
#define T_STEPS 512
#define B_TOTAL 512
#define I_DIM   32
#define H_DIM   64
#define G_DIM   256   // 4*H
#define HX_DIM  96    // concatenated [h(64); x(32)]
#define NT      8     // num tickers

typedef unsigned long long u64;

__device__ __forceinline__ u64 ffma2(u64 a, u64 b, u64 c) {
    u64 d;
    asm("fma.rn.f32x2 %0, %1, %2, %3;" : "=l"(d) : "l"(a), "l"(b), "l"(c));
    return d;
}
__device__ __forceinline__ u64 pack2(float lo, float hi) {
    u64 d;
    asm("mov.b64 %0, {%1, %2};" : "=l"(d) : "f"(lo), "f"(hi));
    return d;
}
__device__ __forceinline__ void unpack2(u64 v, float& lo, float& hi) {
    asm("mov.b64 {%0, %1}, %2;" : "=f"(lo), "=f"(hi) : "l"(v));
}
__device__ __forceinline__ float fast_sigmoid(float x) {
    return 1.0f / (1.0f + __expf(-x));
}
__device__ __forceinline__ float fast_tanh(float x) {
    return 1.0f - 2.0f / (__expf(2.0f * x) + 1.0f);  // stable for large |x|
}

// ---------------------------------------------------------------------------
// Fused LSTM, k-packed SIMD-dot edition.
// 256 CTAs x 256 threads, 2 batches per CTA, __launch_bounds__(256,2) ->
// 2 CTAs/SM (4 warps/SMSP). Thread g in [0,256) owns ONE gate row:
//   weights [W_hh|W_ih][g] packed k-pairwise into 48 u64 (96 regs - no cliff).
//   f32x2 accumulator lanes hold even/odd-k partial sums; folded by lo+hi.
//   Operands hx[b][96] in NATURAL float layout (no duplication); LDS.128
//   reads are warp-broadcast (same address all lanes) -> conflict-free.
// Elementwise: threads 0..127, one cell each; x staging: threads 128..191
// via a depth-4 register prefetch ring (no exposed LDG in the phase).
// Cross-CTA overlap: the co-resident CTA's matvec fills this CTA's
// elementwise/barrier dead time via the warp scheduler.
// ---------------------------------------------------------------------------
__global__ __launch_bounds__(256, 2) void fused_lstm_kernel(
    const float* __restrict__ x,    const float* __restrict__ w_ih,
    const float* __restrict__ w_hh, const float* __restrict__ b_ih,
    const float* __restrict__ b_hh, const float* __restrict__ w_fc,
    const float* __restrict__ b_fc, float* __restrict__ out)
{
    __shared__ __align__(16) float hx[2][HX_DIM];   // [b][0:64)=h, [64:96)=x
    __shared__ __align__(16) float gates[2][G_DIM]; // [b][g]

    const int tid = threadIdx.x;
    const int g   = tid;                 // gate row
    const int B0  = blockIdx.x * 2;

    // ---- pack [W_hh | W_ih] row g, k-pairwise, into 48 u64 regs ----
    u64 w2[48];
    {
        const float* rh = w_hh + g * H_DIM;
        #pragma unroll
        for (int k = 0; k < 32; k++) w2[k] = pack2(rh[2 * k], rh[2 * k + 1]);
        const float* ri = w_ih + g * I_DIM;
        #pragma unroll
        for (int i = 0; i < 16; i++) w2[32 + i] = pack2(ri[2 * i], ri[2 * i + 1]);
    }
    const float bias = b_ih[g] + b_hh[g];

    // ---- elementwise identity: threads 0..127 own cell (be, ke) ----
    const int be = tid >> 6;             // valid for tid < 128
    const int ke = tid & 63;
    float c_val = 0.0f;

    // ---- staging identity: threads 128..191 stage x (bq, iq) ----
    const int  st = tid - 128;
    const bool is_stage = (st >= 0) && (st < 64);
    const int  bq = (st >> 5) & 1, iq = st & 31;
    const float* sx = x + ((size_t)(B0 + bq) * T_STEPS) * I_DIM + iq;
    float xr0 = 0.f, xr1 = 0.f, xr2 = 0.f;

    // ---- init: h = 0 (threads 0..127), x(0) staged, x(1..3) in regs ----
    if (tid < 128) hx[be][ke] = 0.0f;
    if (is_stage) {
        hx[bq][H_DIM + iq] = sx[0];
        xr0 = sx[1 * I_DIM];
        xr1 = sx[2 * I_DIM];
        xr2 = sx[3 * I_DIM];
    }
    __syncthreads();

    const u64* v0 = (const u64*)hx[0];
    const u64* v1 = (const u64*)hx[1];

    for (int t = 0; t < T_STEPS; t++) {
        // ---- SIMD dot: 96-dim [h;x] for both batches (2 indep chains) ----
        u64 acc0 = 0ULL, acc1 = 0ULL;
        #pragma unroll
        for (int k = 0; k < 48; k += 2) {
            ulonglong2 a = *(const ulonglong2*)(v0 + k);
            ulonglong2 b = *(const ulonglong2*)(v1 + k);
            acc0 = ffma2(w2[k], a.x, acc0); acc0 = ffma2(w2[k + 1], a.y, acc0);
            acc1 = ffma2(w2[k], b.x, acc1); acc1 = ffma2(w2[k + 1], b.y, acc1);
        }
        {
            float l0, h0, l1, h1;
            unpack2(acc0, l0, h0);
            unpack2(acc1, l1, h1);
            gates[0][g] = bias + l0 + h0;
            gates[1][g] = bias + l1 + h1;
        }

        __syncthreads();   // gates visible; all hx reads of step t complete

        if (tid < 128) {
            // ---- elementwise cell (be, ke); PyTorch order i,f,g,o ----
            float i_a = fast_sigmoid(gates[be][ke]);
            float f_a = fast_sigmoid(gates[be][64 + ke]);
            float g_a = fast_tanh   (gates[be][128 + ke]);
            float o_a = fast_sigmoid(gates[be][192 + ke]);
            c_val = f_a * c_val + i_a * g_a;
            hx[be][ke] = o_a * fast_tanh(c_val);
        } else if (is_stage) {
            // ---- stage x(t+1) from the ring; refill with x(t+4) ----
            if (t + 1 < T_STEPS) hx[bq][H_DIM + iq] = xr0;
            xr0 = xr1; xr1 = xr2;
            if (t + 4 < T_STEPS) xr2 = sx[(size_t)(t + 4) * I_DIM];
        }

        __syncthreads();   // h(t+1), x(t+1) visible
    }

    // ---- final FC: out[b][n] = h_last[b] . w_fc[n] + b_fc[n] ----
    if (tid < 2 * NT) {
        int b = tid >> 3, n = tid & 7;
        float s = b_fc[n];
        const float* wf = w_fc + n * H_DIM;
        #pragma unroll
        for (int k = 0; k < H_DIM; k++) s += hx[b][k] * wf[k];
        out[(B0 + b) * NT + n] = s;
    }
}

// ---------------------------------------------------------------------------
extern "C" void kernel_launch(void* const* d_in, const int* in_sizes, int n_in,
                              void* d_out, int out_size)
{
    const float* x    = (const float*)d_in[0];
    const float* w_ih = (const float*)d_in[1];
    const float* w_hh = (const float*)d_in[2];
    const float* b_ih = (const float*)d_in[3];
    const float* b_hh = (const float*)d_in[4];
    const float* w_fc = (const float*)d_in[5];
    const float* b_fc = (const float*)d_in[6];
    float* out = (float*)d_out;

    (void)in_sizes; (void)n_in; (void)out_size;

    fused_lstm_kernel<<<B_TOTAL / 2, 256>>>(x, w_ih, w_hh, b_ih, b_hh,
                                            w_fc, b_fc, out);
}